// round 1
// baseline (speedup 1.0000x reference)
#include <cuda_runtime.h>
#include <math.h>

#define NA 48
#define NB 24
#define DIM 286
#define NBATCH 256
#define NMU 6
#define L5OFF 165

// Scratch (static device globals; no allocation)
__device__ float g_c[NA * NMU];     // cos-like per (x, mu), l-independent
__device__ float g_s[NA * NMU];     // sin-like per (x, mu)
__device__ float g_act;             // normalize2mom constant for tanh
__device__ float g_part[1024];      // partial sums for the activation integral

__constant__ int c_off[6] = {0, 1, 10, 35, 84, 165};

// ---------------------------------------------------------------------------
// Replicate reference ACT_CST = (trapz over 1e6+1 pts of tanh(x)^2 * N(0,1))^-1/2
// ---------------------------------------------------------------------------
__global__ void act_kernel() {
    int tid = blockIdx.x * blockDim.x + threadIdx.x;  // 1024*256 = 262144 threads
    float sum = 0.f;
    for (int i = tid; i <= 1000000; i += 262144) {
        float x = -12.f + (float)i * 2.4e-5f;
        float t = tanhf(x);
        float p = __expf(-0.5f * x * x);  // fast exp fine: ~1e-7 rel, averages out
        sum += t * t * p;
    }
    for (int o = 16; o; o >>= 1) sum += __shfl_down_sync(0xffffffffu, sum, o);
    __shared__ float ws[8];
    int w = threadIdx.x >> 5;
    if ((threadIdx.x & 31) == 0) ws[w] = sum;
    __syncthreads();
    if (threadIdx.x == 0) {
        float b = 0.f;
        for (int i = 0; i < 8; i++) b += ws[i];
        g_part[blockIdx.x] = b;
    }
}

// ---------------------------------------------------------------------------
// Prep: extract per-sector 2x2 alpha-rotation (c,s) from the l=5 block of D,
// using Ra5[x] = D5[x,0,0] * D5[0,0,0]^T / 11  (Rb orthogonal, Ra(0)=I).
// Also finish the ACT_CST reduction.
// ---------------------------------------------------------------------------
__global__ void prep_kernel(const float* __restrict__ D) {
    int t = threadIdx.x;
    if (t < NA * NMU) {
        int x = t / NMU, mu = t % NMU;
        int p0 = 5 - mu, p1 = 5 + mu;
        const float* X = D + (size_t)x * NB * NA * DIM + L5OFF;  // D[x][0][0][l=5 block]
        const float* Z = D + L5OFF;                              // D[0][0][0][l=5 block]
        float a00 = 0.f, a01 = 0.f, a10 = 0.f, a11 = 0.f;
        for (int k = 0; k < 11; k++) {
            float xp0 = X[p0 * 11 + k], xp1 = X[p1 * 11 + k];
            float zp0 = Z[p0 * 11 + k], zp1 = Z[p1 * 11 + k];
            a00 += xp0 * zp0; a01 += xp0 * zp1;
            a10 += xp1 * zp0; a11 += xp1 * zp1;
        }
        const float inv11 = 1.f / 11.f;
        g_c[t] = 0.5f * (a00 + a11) * inv11;
        g_s[t] = 0.5f * (a01 - a10) * inv11;
    }
    if (t == 0) {
        float tot = 0.f;
        for (int i = 0; i < 1024; i++) tot += g_part[i];
        float I = tot * 2.4e-5f * 0.3989422804014327f;  // dx * 1/sqrt(2pi)
        g_act = 1.0f / sqrtf(I);
    }
}

__global__ void zero_kernel(float* out, int n) {
    int i = blockIdx.x * blockDim.x + threadIdx.x;
    if (i < n) out[i] = 0.f;
}

// ---------------------------------------------------------------------------
// Main: one CTA per (batch b, beta index y).
//   P[mu][nu][4]  : features x Rb[y]-block trace forms
//   T stage       : contract nu with (c,s)(z)
//   synth         : g[x][z] = sum_mu c_x T0 + s_x T1 ; tanh ; * qw
//   U stage       : contract x with (c,s)
//   Q[mu][nu][4]  : contract z with (c,s)
//   out           : scatter Q x Rb[y]-blocks into out[b,:] (atomicAdd over y)
// ---------------------------------------------------------------------------
__global__ __launch_bounds__(256) void so3_main(const float* __restrict__ feat,
                                                const float* __restrict__ D,
                                                const float* __restrict__ qw,
                                                float* __restrict__ out) {
    const int b = blockIdx.x / NB;
    const int y = blockIdx.x % NB;
    const int t = threadIdx.x;

    __shared__ float sF[DIM];
    __shared__ float sB[DIM];
    __shared__ float scs[NA * NMU];
    __shared__ float ssn[NA * NMU];
    __shared__ float sP[4][NMU][NMU];
    __shared__ float sT0[NMU][NA];
    __shared__ float sT1[NMU][NA];
    __shared__ float sG[NA][NA + 1];
    __shared__ float sU0[NMU][NA];
    __shared__ float sU1[NMU][NA];
    __shared__ float sQ[4][NMU][NMU];

    for (int i = t; i < DIM; i += 256) {
        sF[i] = feat[b * DIM + i];
        sB[i] = D[(size_t)y * NA * DIM + i];  // D[0][y][0][i]  (includes sqrt(2l+1))
    }
    for (int i = t; i < NA * NMU; i += 256) {
        scs[i] = g_c[i];
        ssn[i] = g_s[i];
    }
    __syncthreads();

    // --- P forms -----------------------------------------------------------
    if (t < 36) {
        int mu = t / 6, nu = t % 6;
        float P00 = 0.f, P01 = 0.f, P10 = 0.f, P11 = 0.f;
        int l0 = mu > nu ? mu : nu;
        for (int l = l0; l <= 5; l++) {
            int dl = 2 * l + 1, off = c_off[l];
            int r0 = l - mu, r1 = l + mu, q0 = l - nu, q1 = l + nu;
            float F00 = sF[off + r0 * dl + q0], F01 = sF[off + r0 * dl + q1];
            float F10 = sF[off + r1 * dl + q0], F11 = sF[off + r1 * dl + q1];
            float B00 = sB[off + r0 * dl + q0], B01 = sB[off + r0 * dl + q1];
            float B10 = sB[off + r1 * dl + q0], B11 = sB[off + r1 * dl + q1];
            if (mu == 0) { F10 = F11 = 0.f; B10 = B11 = 0.f; }
            if (nu == 0) { F01 = F11 = 0.f; B01 = B11 = 0.f; }
            P00 +=  F00 * B00 + F01 * B01 + F10 * B10 + F11 * B11;
            P01 += -F00 * B01 + F01 * B00 - F10 * B11 + F11 * B10;
            P10 +=  F00 * B10 + F01 * B11 - F10 * B00 - F11 * B01;
            P11 += -F00 * B11 + F01 * B10 + F10 * B01 - F11 * B00;
        }
        sP[0][mu][nu] = P00; sP[1][mu][nu] = P01;
        sP[2][mu][nu] = P10; sP[3][mu][nu] = P11;
    }
    __syncthreads();

    // --- T stage: contract nu with z-trig ---------------------------------
    for (int i = t; i < NMU * NA; i += 256) {
        int mu = i / NA, z = i % NA;
        float t0 = 0.f, t1 = 0.f;
#pragma unroll
        for (int nu = 0; nu < NMU; nu++) {
            float cz = scs[z * NMU + nu], sz = ssn[z * NMU + nu];
            t0 += sP[0][mu][nu] * cz + sP[1][mu][nu] * sz;
            t1 += sP[2][mu][nu] * cz + sP[3][mu][nu] * sz;
        }
        sT0[mu][z] = t0;
        sT1[mu][z] = t1;
    }
    __syncthreads();

    // --- synthesis + activation -------------------------------------------
    const float inv_s = 1.f / sqrtf(286.f);
    const float actq = g_act * qw[y];
    if (t < 192) {
        int x = t >> 2, j = t & 3;
        float cx[NMU], sx[NMU];
#pragma unroll
        for (int mu = 0; mu < NMU; mu++) {
            cx[mu] = scs[x * NMU + mu];
            sx[mu] = ssn[x * NMU + mu];
        }
        for (int z = j; z < NA; z += 4) {
            float g = 0.f;
#pragma unroll
            for (int mu = 0; mu < NMU; mu++)
                g += cx[mu] * sT0[mu][z] + sx[mu] * sT1[mu][z];
            sG[x][z] = actq * tanhf(g * inv_s);
        }
    }
    __syncthreads();

    // --- U stage: contract x with trig ------------------------------------
    for (int i = t; i < NMU * NA; i += 256) {
        int mu = i / NA, z = i % NA;
        float u0 = 0.f, u1 = 0.f;
        for (int x = 0; x < NA; x++) {
            float g = sG[x][z];
            u0 += scs[x * NMU + mu] * g;
            u1 += ssn[x * NMU + mu] * g;
        }
        sU0[mu][z] = u0;
        sU1[mu][z] = u1;
    }
    __syncthreads();

    // --- Q forms: contract z with trig ------------------------------------
    if (t < 144) {
        int comp = t / 36, r = t % 36;
        int mu = r / 6, nu = r % 6;
        const float(*U)[NA] = (comp < 2) ? sU0 : sU1;
        float q = 0.f;
        for (int z = 0; z < NA; z++)
            q += U[mu][z] * ((comp & 1) ? ssn[z * NMU + nu] : scs[z * NMU + nu]);
        sQ[comp][mu][nu] = q;
    }
    __syncthreads();

    // --- scatter into out --------------------------------------------------
    const float sscale = sqrtf(286.f);
    if (t < 36) {
        int mu = t / 6, nu = t % 6;
        float Q00 = sQ[0][mu][nu], Q01 = sQ[1][mu][nu];
        float Q10 = sQ[2][mu][nu], Q11 = sQ[3][mu][nu];
        int l0 = mu > nu ? mu : nu;
        float* ob = out + (size_t)b * DIM;
        for (int l = l0; l <= 5; l++) {
            int dl = 2 * l + 1, off = c_off[l];
            int r0 = l - mu, r1 = l + mu, q0 = l - nu, q1 = l + nu;
            float B00 = sB[off + r0 * dl + q0], B01 = sB[off + r0 * dl + q1];
            float B10 = sB[off + r1 * dl + q0], B11 = sB[off + r1 * dl + q1];
            if (mu == 0) { B10 = B11 = 0.f; }
            if (nu == 0) { B01 = B11 = 0.f; }
            float o00 = Q00 * B00 - Q01 * B01 + Q10 * B10 - Q11 * B11;
            float o01 = Q00 * B01 + Q01 * B00 + Q10 * B11 + Q11 * B10;
            float o10 = Q00 * B10 - Q01 * B11 - Q10 * B00 + Q11 * B01;
            float o11 = Q00 * B11 + Q01 * B10 - Q10 * B01 - Q11 * B00;
            atomicAdd(&ob[off + r0 * dl + q0], sscale * o00);
            if (nu > 0) atomicAdd(&ob[off + r0 * dl + q1], sscale * o01);
            if (mu > 0) atomicAdd(&ob[off + r1 * dl + q0], sscale * o10);
            if (mu > 0 && nu > 0) atomicAdd(&ob[off + r1 * dl + q1], sscale * o11);
        }
    }
}

extern "C" void kernel_launch(void* const* d_in, const int* in_sizes, int n_in,
                              void* d_out, int out_size) {
    const float* feat = (const float*)d_in[0];  // [256, 286]
    const float* D    = (const float*)d_in[1];  // [48, 24, 48, 286]
    const float* qw   = (const float*)d_in[2];  // [24]
    float* out        = (float*)d_out;          // [256, 286]

    act_kernel<<<1024, 256>>>();
    prep_kernel<<<1, 512>>>(D);
    zero_kernel<<<(NBATCH * DIM + 255) / 256, 256>>>(out, NBATCH * DIM);
    so3_main<<<NBATCH * NB, 256>>>(feat, D, qw, out);
}